// round 2
// baseline (speedup 1.0000x reference)
#include <cuda_runtime.h>
#include <cstdint>

// Problem constants (BSZ=1)
#define SEQn   2048
#define Hn     128
#define DNOPE  128
#define DROPE  64
#define DQK    192      // D_NOPE + D_ROPE
#define DKV    256      // D_NOPE + D_V
#define VQK    (DQK/4)  // 48 float4 per row
#define VKV    (DKV/4)  // 64 float4 per row

// ---------------------------------------------------------------------------
// Kernel 1: q_out = concat(q_nope, rope(q_pe))   shape (SEQ, H, 192)
// Flat float4 indexing; layout of q and q_out is identical.
// ---------------------------------------------------------------------------
__global__ void __launch_bounds__(256)
q_rope_kernel(const float4* __restrict__ q,
              const float*  __restrict__ cos_t,
              const float*  __restrict__ sin_t,
              const int*    __restrict__ pos,     // int32 (JAX x64 disabled)
              float4* __restrict__ out)
{
    long long vid = (long long)blockIdx.x * blockDim.x + threadIdx.x;
    const long long total = (long long)SEQn * Hn * VQK;
    if (vid >= total) return;

    int c4  = (int)(vid % VQK);
    int col = c4 * 4;
    float4 x = __ldg(&q[vid]);

    if (col < DNOPE) {
        out[vid] = x;
    } else {
        long long row = vid / VQK;        // (s*H + h)
        int s = (int)(row / Hn);
        int p = __ldg(&pos[s]);
        int d  = col - DNOPE;             // 0..60, step 4
        int pd = (d < 32) ? d + 32 : d - 32;
        float sgn = (d < 32) ? -1.0f : 1.0f;

        const float4* qrope = q + row * VQK + (DNOPE/4);
        float4 xp = __ldg(&qrope[pd >> 2]);
        float4 c  = __ldg((const float4*)(cos_t + (long long)p * DROPE) + (d >> 2));
        float4 sn = __ldg((const float4*)(sin_t + (long long)p * DROPE) + (d >> 2));

        float4 r;
        r.x = fmaf(sgn * xp.x, sn.x, x.x * c.x);
        r.y = fmaf(sgn * xp.y, sn.y, x.y * c.y);
        r.z = fmaf(sgn * xp.z, sn.z, x.z * c.z);
        r.w = fmaf(sgn * xp.w, sn.w, x.w * c.w);
        out[vid] = r;
    }
}

// ---------------------------------------------------------------------------
// Kernel 2: res_kv shape (SEQ, 2, H, 192)
//   slot 0: [kv[..., :128], rope(k_pe) broadcast over h]
//   slot 1: [kv[..., 128:256], zeros(64)]
// ---------------------------------------------------------------------------
__global__ void __launch_bounds__(256)
kv_kernel(const float4* __restrict__ kv,
          const float4* __restrict__ k_pe,      // (SEQ, 64) -> 16 float4 per s
          const float*  __restrict__ cos_t,
          const float*  __restrict__ sin_t,
          const int*    __restrict__ pos,
          float4* __restrict__ out)
{
    long long vid = (long long)blockIdx.x * blockDim.x + threadIdx.x;
    const long long total = (long long)SEQn * 2 * Hn * VQK;
    if (vid >= total) return;

    int c4        = (int)(vid % VQK);
    long long rw  = vid / VQK;           // ((s*2 + slot)*H + h)
    int h         = (int)(rw % Hn);
    long long ss  = rw / Hn;             // s*2 + slot
    int slot      = (int)(ss & 1);
    int s         = (int)(ss >> 1);
    int col       = c4 * 4;

    float4 r;
    if (col < DNOPE) {
        // kv row = 64 float4; slot 0 -> nope half (offset 0), slot 1 -> value half (offset 32)
        long long kvbase = ((long long)s * Hn + h) * VKV;
        r = __ldg(&kv[kvbase + slot * (DNOPE/4) + (col >> 2)]);
    } else if (slot == 0) {
        // rope(k_pe[s]) broadcast across h
        int p = __ldg(&pos[s]);
        int d  = col - DNOPE;
        int pd = (d < 32) ? d + 32 : d - 32;
        float sgn = (d < 32) ? -1.0f : 1.0f;

        const float4* kp = k_pe + (long long)s * (DROPE/4);
        float4 x  = __ldg(&kp[d >> 2]);
        float4 xp = __ldg(&kp[pd >> 2]);
        float4 c  = __ldg((const float4*)(cos_t + (long long)p * DROPE) + (d >> 2));
        float4 sn = __ldg((const float4*)(sin_t + (long long)p * DROPE) + (d >> 2));

        r.x = fmaf(sgn * xp.x, sn.x, x.x * c.x);
        r.y = fmaf(sgn * xp.y, sn.y, x.y * c.y);
        r.z = fmaf(sgn * xp.z, sn.z, x.z * c.z);
        r.w = fmaf(sgn * xp.w, sn.w, x.w * c.w);
    } else {
        r = make_float4(0.0f, 0.0f, 0.0f, 0.0f);
    }
    out[vid] = r;
}

extern "C" void kernel_launch(void* const* d_in, const int* in_sizes, int n_in,
                              void* d_out, int out_size)
{
    const float4* q     = (const float4*)d_in[0];
    const float4* kv    = (const float4*)d_in[1];
    const float4* k_pe  = (const float4*)d_in[2];
    const float*  cos_t = (const float*)d_in[3];
    const float*  sin_t = (const float*)d_in[4];
    const int*    pos   = (const int*)d_in[5];

    float4* out_q  = (float4*)d_out;
    float4* out_kv = out_q + (long long)SEQn * Hn * VQK;

    const long long nq  = (long long)SEQn * Hn * VQK;            // 12,582,912
    const long long nkv = (long long)SEQn * 2 * Hn * VQK;        // 25,165,824

    const int T = 256;
    q_rope_kernel<<<(unsigned)((nq  + T - 1) / T), T>>>(q, cos_t, sin_t, pos, out_q);
    kv_kernel   <<<(unsigned)((nkv + T - 1) / T), T>>>(kv, k_pe, cos_t, sin_t, pos, out_kv);
}